// round 1
// baseline (speedup 1.0000x reference)
#include <cuda_runtime.h>

// Problem constants
#define BATCH 2
#define SEQ   2048
#define DMODEL 1024
#define NHEAD 16
#define DHEAD 64
#define SP    2048           // queries per head after the seq-split reshape
#define SCALE_INV 0.03125f   // 1/sqrt(1024)

// Scratch for projected Q,K,V (allocation-free rule: __device__ globals)
__device__ float g_Q[BATCH * SEQ * DMODEL];
__device__ float g_K[BATCH * SEQ * DMODEL];
__device__ float g_V[BATCH * SEQ * DMODEL];

// ---------------------------------------------------------------------------
// Projection: Y = X @ W^T.  X: [4096, 1024], W: [1024, 1024] (row = out feat).
// 64x64 output tile, 256 threads, 4x4 microtile, K-chunks of 64.
// blockIdx.z selects {Wq->g_Q, Wk->g_K, Wv->g_V}.
// ---------------------------------------------------------------------------
__global__ __launch_bounds__(256) void proj_kernel(
    const float* __restrict__ X,
    const float* __restrict__ Wq,
    const float* __restrict__ Wk,
    const float* __restrict__ Wv)
{
    __shared__ float Xs[64][65];
    __shared__ float Ws[64][65];

    const int bz = blockIdx.z;
    const float* __restrict__ W = (bz == 0) ? Wq : (bz == 1) ? Wk : Wv;
    float* __restrict__ Y = (bz == 0) ? g_Q : (bz == 1) ? g_K : g_V;

    const int rowBase = blockIdx.y * 64;   // over 4096 (B*S)
    const int colBase = blockIdx.x * 64;   // over 1024 (out features)
    const int tid = threadIdx.x;
    const int tx = tid & 15;
    const int ty = tid >> 4;

    float c[4][4] = {};

    for (int k0 = 0; k0 < DMODEL; k0 += 64) {
        __syncthreads();
        // Load 64x64 tiles of X and W (coalesced float4 global loads)
        for (int i = tid; i < 64 * 16; i += 256) {
            const int r  = i >> 4;
            const int c4 = (i & 15) << 2;
            float4 xv = *(const float4*)(X + (size_t)(rowBase + r) * DMODEL + k0 + c4);
            Xs[r][c4 + 0] = xv.x; Xs[r][c4 + 1] = xv.y;
            Xs[r][c4 + 2] = xv.z; Xs[r][c4 + 3] = xv.w;
            float4 wv = *(const float4*)(W + (size_t)(colBase + r) * DMODEL + k0 + c4);
            Ws[r][c4 + 0] = wv.x; Ws[r][c4 + 1] = wv.y;
            Ws[r][c4 + 2] = wv.z; Ws[r][c4 + 3] = wv.w;
        }
        __syncthreads();

        #pragma unroll 16
        for (int kk = 0; kk < 64; kk++) {
            float a[4], b[4];
            #pragma unroll
            for (int i = 0; i < 4; i++) a[i] = Xs[ty * 4 + i][kk];
            #pragma unroll
            for (int j = 0; j < 4; j++) b[j] = Ws[tx * 4 + j][kk];
            #pragma unroll
            for (int i = 0; i < 4; i++)
                #pragma unroll
                for (int j = 0; j < 4; j++)
                    c[i][j] = fmaf(a[i], b[j], c[i][j]);
        }
    }

    #pragma unroll
    for (int i = 0; i < 4; i++) {
        float4 st = make_float4(c[i][0], c[i][1], c[i][2], c[i][3]);
        *(float4*)(Y + (size_t)(rowBase + ty * 4 + i) * DMODEL + colBase + tx * 4) = st;
    }
}

// ---------------------------------------------------------------------------
// Attention per (b,h). Because the reference reshape splits the flattened
// (S,D) space, head h's q/k/v are CONTIGUOUS [2048,64] row-major matrices at
// offset b*S*D + h*128*1024 inside g_Q/g_K/g_V.
//
// Block: 64-query tile, 256 threads (16x16), 4x4 microtiles.
// Phase 1: loop 32 K-tiles, compute scaled logits, write RAW logits to the
//          sim output region, keep running row max/sum in registers
//          (replicated across each 16-lane group via shuffle reductions).
// Phase 2: loop 32 K-tiles again, re-read raw logits (same thread wrote them),
//          normalize, write final probabilities, accumulate O += P @ V.
// ---------------------------------------------------------------------------
__global__ __launch_bounds__(256) void attn_kernel(
    float* __restrict__ out_attn,   // [B, S, D]
    float* __restrict__ out_sim)    // [B, H, SP, SP]
{
    __shared__ float bufA[64][65];  // Q tile (phase 1) / P tile (phase 2)
    __shared__ float bufB[64][65];  // K tile (phase 1) / V tile (phase 2)

    const int qt = blockIdx.x;      // 0..31 query tiles
    const int h  = blockIdx.y;      // 0..15
    const int b  = blockIdx.z;      // 0..1

    const size_t headOff = ((size_t)b * SEQ + (size_t)h * 128) * DMODEL;
    const float* __restrict__ Qh = g_Q + headOff;   // [2048, 64] contiguous
    const float* __restrict__ Kh = g_K + headOff;
    const float* __restrict__ Vh = g_V + headOff;
    float* __restrict__ simB = out_sim + ((size_t)(b * NHEAD + h)) * SP * SP;

    const int tid = threadIdx.x;
    const int tx = tid & 15;
    const int ty = tid >> 4;

    // Load Q tile (64 rows x 64 dims)
    for (int i = tid; i < 64 * 16; i += 256) {
        const int r  = i >> 4;
        const int c4 = (i & 15) << 2;
        float4 v = *(const float4*)(Qh + ((size_t)(qt * 64 + r) << 6) + c4);
        bufA[r][c4 + 0] = v.x; bufA[r][c4 + 1] = v.y;
        bufA[r][c4 + 2] = v.z; bufA[r][c4 + 3] = v.w;
    }

    // Running softmax state, replicated across the 16-lane row group
    float m[4], den[4];
    #pragma unroll
    for (int i = 0; i < 4; i++) { m[i] = -1e30f; den[i] = 0.0f; }

    // ---------------- Phase 1: logits + running max/sum ----------------
    for (int kt = 0; kt < 32; kt++) {
        __syncthreads();
        for (int i = tid; i < 64 * 16; i += 256) {
            const int r  = i >> 4;
            const int c4 = (i & 15) << 2;
            float4 v = *(const float4*)(Kh + ((size_t)(kt * 64 + r) << 6) + c4);
            bufB[r][c4 + 0] = v.x; bufB[r][c4 + 1] = v.y;
            bufB[r][c4 + 2] = v.z; bufB[r][c4 + 3] = v.w;
        }
        __syncthreads();

        float c[4][4] = {};
        #pragma unroll 16
        for (int kk = 0; kk < 64; kk++) {
            float a[4], kv[4];
            #pragma unroll
            for (int i = 0; i < 4; i++) a[i] = bufA[ty * 4 + i][kk];
            #pragma unroll
            for (int j = 0; j < 4; j++) kv[j] = bufB[tx * 4 + j][kk];
            #pragma unroll
            for (int i = 0; i < 4; i++)
                #pragma unroll
                for (int j = 0; j < 4; j++)
                    c[i][j] = fmaf(a[i], kv[j], c[i][j]);
        }

        #pragma unroll
        for (int i = 0; i < 4; i++) {
            // scale
            #pragma unroll
            for (int j = 0; j < 4; j++) c[i][j] *= SCALE_INV;

            // write raw logits (float4, coalesced across tx)
            const int q = qt * 64 + ty * 4 + i;
            float4 st = make_float4(c[i][0], c[i][1], c[i][2], c[i][3]);
            *(float4*)(simB + (size_t)q * SP + kt * 64 + tx * 4) = st;

            // tile max over this row (reduce across 16-lane group)
            float tm = fmaxf(fmaxf(c[i][0], c[i][1]), fmaxf(c[i][2], c[i][3]));
            #pragma unroll
            for (int o = 8; o > 0; o >>= 1)
                tm = fmaxf(tm, __shfl_xor_sync(0xffffffffu, tm, o, 16));

            const float mo = m[i];
            const float mn = fmaxf(mo, tm);
            float ts = __expf(c[i][0] - mn) + __expf(c[i][1] - mn) +
                       __expf(c[i][2] - mn) + __expf(c[i][3] - mn);
            #pragma unroll
            for (int o = 8; o > 0; o >>= 1)
                ts += __shfl_xor_sync(0xffffffffu, ts, o, 16);

            den[i] = den[i] * __expf(mo - mn) + ts;
            m[i]   = mn;
        }
    }

    float inv[4];
    #pragma unroll
    for (int i = 0; i < 4; i++) inv[i] = 1.0f / den[i];

    // ---------------- Phase 2: normalize + P @ V ----------------
    float o[4][4] = {};
    for (int kt = 0; kt < 32; kt++) {
        __syncthreads();   // previous tile's FMA reads done before overwrite

        // Load V tile: bufB[key][dh]
        for (int i = tid; i < 64 * 16; i += 256) {
            const int r  = i >> 4;
            const int c4 = (i & 15) << 2;
            float4 v = *(const float4*)(Vh + ((size_t)(kt * 64 + r) << 6) + c4);
            bufB[r][c4 + 0] = v.x; bufB[r][c4 + 1] = v.y;
            bufB[r][c4 + 2] = v.z; bufB[r][c4 + 3] = v.w;
        }

        // Re-read raw logits (written by THIS thread in phase 1 -> coherent),
        // normalize, write final probabilities, stage P tile into bufA.
        #pragma unroll
        for (int i = 0; i < 4; i++) {
            const int r = ty * 4 + i;
            const int q = qt * 64 + r;
            float4 l4 = *(const float4*)(simB + (size_t)q * SP + kt * 64 + tx * 4);
            float4 p;
            p.x = __expf(l4.x - m[i]) * inv[i];
            p.y = __expf(l4.y - m[i]) * inv[i];
            p.z = __expf(l4.z - m[i]) * inv[i];
            p.w = __expf(l4.w - m[i]) * inv[i];
            *(float4*)(simB + (size_t)q * SP + kt * 64 + tx * 4) = p;
            bufA[r][tx * 4 + 0] = p.x; bufA[r][tx * 4 + 1] = p.y;
            bufA[r][tx * 4 + 2] = p.z; bufA[r][tx * 4 + 3] = p.w;
        }
        __syncthreads();

        // O += P @ V  (dot over 64 keys of this tile)
        #pragma unroll 16
        for (int kk = 0; kk < 64; kk++) {
            float a[4], vv[4];
            #pragma unroll
            for (int i = 0; i < 4; i++) a[i] = bufA[ty * 4 + i][kk];
            #pragma unroll
            for (int j = 0; j < 4; j++) vv[j] = bufB[kk][tx * 4 + j];
            #pragma unroll
            for (int i = 0; i < 4; i++)
                #pragma unroll
                for (int j = 0; j < 4; j++)
                    o[i][j] = fmaf(a[i], vv[j], o[i][j]);
        }
    }

    // Write self_attn with the (0,2,1,3) transpose:
    // out[b][s'][h*64 + dh], s' = qt*64 + ty*4 + i, dh = tx*4 + j
    #pragma unroll
    for (int i = 0; i < 4; i++) {
        const int sp = qt * 64 + ty * 4 + i;
        float4 st = make_float4(o[i][0], o[i][1], o[i][2], o[i][3]);
        *(float4*)(out_attn + ((size_t)b * SEQ + sp) * DMODEL + h * DHEAD + tx * 4) = st;
    }
}

// ---------------------------------------------------------------------------
extern "C" void kernel_launch(void* const* d_in, const int* in_sizes, int n_in,
                              void* d_out, int out_size)
{
    const float* seq = (const float*)d_in[0];
    const float* Wq  = (const float*)d_in[1];
    const float* Wk  = (const float*)d_in[2];
    const float* Wv  = (const float*)d_in[3];

    float* out_attn = (float*)d_out;                              // [B,S,D]
    float* out_sim  = (float*)d_out + (size_t)BATCH * SEQ * DMODEL; // [B,H,SP,SP]

    // Projections: Q,K,V = seq @ W^T  (grid.z selects weight/output)
    proj_kernel<<<dim3(DMODEL / 64, (BATCH * SEQ) / 64, 3), 256>>>(seq, Wq, Wk, Wv);

    // Fused attention + softmax (writes both outputs)
    attn_kernel<<<dim3(SP / 64, NHEAD, BATCH), 256>>>(out_attn, out_sim);
}

// round 2
// speedup vs baseline: 1.0891x; 1.0891x over previous
#include <cuda_runtime.h>

#define BATCH 2
#define SEQ   2048
#define DMODEL 1024
#define NHEAD 16
#define DHEAD 64
#define SCALE_INV 0.03125f   // 1/sqrt(1024)

typedef unsigned long long u64;

// Scratch for projected Q,K,V (allocation-free rule: __device__ globals)
__device__ float g_Q[BATCH * SEQ * DMODEL];
__device__ float g_K[BATCH * SEQ * DMODEL];
__device__ float g_V[BATCH * SEQ * DMODEL];

// ---- packed f32x2 helpers (Blackwell sm_103a) ------------------------------
__device__ __forceinline__ u64 ffma2(u64 a, u64 b, u64 c) {
    u64 d; asm("fma.rn.f32x2 %0, %1, %2, %3;" : "=l"(d) : "l"(a), "l"(b), "l"(c));
    return d;
}
__device__ __forceinline__ u64 pack2(float lo, float hi) {
    u64 r; asm("mov.b64 %0, {%1, %2};" : "=l"(r) : "f"(lo), "f"(hi));
    return r;
}
__device__ __forceinline__ float2 unpack2(u64 v) {
    float2 r; asm("mov.b64 {%0, %1}, %2;" : "=f"(r.x), "=f"(r.y) : "l"(v));
    return r;
}
__device__ __forceinline__ void f4u(const float4 v, u64& p0, u64& p1) {
    p0 = pack2(v.x, v.y); p1 = pack2(v.z, v.w);
}
__device__ __forceinline__ float psum(u64 v) { float2 t = unpack2(v); return t.x + t.y; }

// XOR-swizzled float offset for (row, float4-group g) in a [64][64] f32 tile.
// Guarantees conflict-free STS.128 and LDS.128 for all access patterns used.
__device__ __forceinline__ int swz(int row, int g) {
    return row * 64 + ((g ^ ((row >> 2) & 7)) << 2);
}

// Load a 64x64 f32 tile (gmem row stride ldg floats) into swizzled smem.
__device__ __forceinline__ void load_tile(float* S, const float* g, int ldg, int tid) {
    #pragma unroll
    for (int it = 0; it < 8; it++) {
        int i  = tid + it * 128;
        int r  = i >> 4;
        int c4 = (i & 15) << 2;
        float4 v = *(const float4*)(g + (size_t)r * ldg + c4);
        *(float4*)&S[swz(r, c4 >> 2)] = v;
    }
}

// ---------------------------------------------------------------------------
// Projection: Y = X @ W^T.  X:[4096,1024], W:[1024,1024] row-major.
// 64x64 tile, 128 threads, 8x4 microtile, k-vectorized f32x2 FMAs.
// ---------------------------------------------------------------------------
__global__ __launch_bounds__(128) void proj_kernel(
    const float* __restrict__ X,
    const float* __restrict__ Wq,
    const float* __restrict__ Wk,
    const float* __restrict__ Wv)
{
    __shared__ float sA[64 * 64];
    __shared__ float sB[64 * 64];

    const int bz = blockIdx.z;
    const float* __restrict__ W = (bz == 0) ? Wq : (bz == 1) ? Wk : Wv;
    float* __restrict__ Y = (bz == 0) ? g_Q : (bz == 1) ? g_K : g_V;

    const int rowBase = blockIdx.y * 64;
    const int colBase = blockIdx.x * 64;
    const int tid = threadIdx.x;
    const int tx = tid & 15;
    const int ty = tid >> 4;

    u64 c2[8][4] = {};   // (even-k, odd-k) partial pairs

    for (int k0 = 0; k0 < DMODEL; k0 += 64) {
        __syncthreads();
        load_tile(sA, X + (size_t)rowBase * DMODEL + k0, DMODEL, tid);
        load_tile(sB, W + (size_t)colBase * DMODEL + k0, DMODEL, tid);
        __syncthreads();

        #pragma unroll
        for (int g = 0; g < 16; g++) {
            u64 bp[4][2];
            #pragma unroll
            for (int j = 0; j < 4; j++) {
                float4 bf = *(const float4*)&sB[swz(tx * 4 + j, g)];
                f4u(bf, bp[j][0], bp[j][1]);
            }
            #pragma unroll
            for (int i = 0; i < 8; i++) {
                const int row = (i < 4) ? ty * 4 + i : 32 + ty * 4 + (i - 4);
                float4 av = *(const float4*)&sA[swz(row, g)];
                u64 a0, a1; f4u(av, a0, a1);
                #pragma unroll
                for (int j = 0; j < 4; j++) {
                    c2[i][j] = ffma2(a0, bp[j][0], c2[i][j]);
                    c2[i][j] = ffma2(a1, bp[j][1], c2[i][j]);
                }
            }
        }
    }

    #pragma unroll
    for (int i = 0; i < 8; i++) {
        const int row = (i < 4) ? ty * 4 + i : 32 + ty * 4 + (i - 4);
        float4 o = make_float4(psum(c2[i][0]), psum(c2[i][1]),
                               psum(c2[i][2]), psum(c2[i][3]));
        *(float4*)(Y + (size_t)(rowBase + row) * DMODEL + colBase + tx * 4) = o;
    }
}

// ---------------------------------------------------------------------------
// Attention per (b,h): head h's q/k/v are CONTIGUOUS [2048,64] matrices.
// Block: 64-query tile, 128 threads, 8x4 microtiles, f32x2 FMAs.
// Phase 1: QK^T logits -> raw logits to sim region + running max/sum.
// Phase 2: re-read, normalize, write probs, O += P@V (P staged transposed).
// ---------------------------------------------------------------------------
__global__ __launch_bounds__(128) void attn_kernel(
    float* __restrict__ out_attn,   // [B, S, D]
    float* __restrict__ out_sim)    // [B, H, S, S]
{
    __shared__ float sA[64 * 64];   // Q tile (ph1) / Pt tile (ph2)
    __shared__ float sB[64 * 64];   // K tile (ph1) / V tile (ph2)

    const int qt = blockIdx.x;      // 0..31
    const int h  = blockIdx.y;
    const int b  = blockIdx.z;

    const size_t headOff = ((size_t)b * SEQ + (size_t)h * 128) * DMODEL;
    const float* __restrict__ Qh = g_Q + headOff;
    const float* __restrict__ Kh = g_K + headOff;
    const float* __restrict__ Vh = g_V + headOff;
    float* __restrict__ simB = out_sim + (size_t)(b * NHEAD + h) * SEQ * SEQ;

    const int tid = threadIdx.x;
    const int tx = tid & 15;
    const int ty = tid >> 4;

    // Q tile: 64 rows x 64 dh
    load_tile(sA, Qh + (size_t)qt * 64 * DHEAD, DHEAD, tid);

    float m[8], den[8];
    #pragma unroll
    for (int i = 0; i < 8; i++) { m[i] = -1e30f; den[i] = 0.0f; }

    // ---------------- Phase 1: logits + running max/sum ----------------
    for (int kt = 0; kt < 32; kt++) {
        __syncthreads();
        load_tile(sB, Kh + (size_t)kt * 64 * DHEAD, DHEAD, tid);
        __syncthreads();

        u64 c2[8][4] = {};
        #pragma unroll
        for (int g = 0; g < 16; g++) {
            u64 bp[4][2];
            #pragma unroll
            for (int j = 0; j < 4; j++) {
                float4 bf = *(const float4*)&sB[swz(tx * 4 + j, g)];
                f4u(bf, bp[j][0], bp[j][1]);
            }
            #pragma unroll
            for (int i = 0; i < 8; i++) {
                const int row = (i < 4) ? ty * 4 + i : 32 + ty * 4 + (i - 4);
                float4 av = *(const float4*)&sA[swz(row, g)];
                u64 a0, a1; f4u(av, a0, a1);
                #pragma unroll
                for (int j = 0; j < 4; j++) {
                    c2[i][j] = ffma2(a0, bp[j][0], c2[i][j]);
                    c2[i][j] = ffma2(a1, bp[j][1], c2[i][j]);
                }
            }
        }

        #pragma unroll
        for (int i = 0; i < 8; i++) {
            const int row = (i < 4) ? ty * 4 + i : 32 + ty * 4 + (i - 4);
            float4 lv = make_float4(psum(c2[i][0]) * SCALE_INV,
                                    psum(c2[i][1]) * SCALE_INV,
                                    psum(c2[i][2]) * SCALE_INV,
                                    psum(c2[i][3]) * SCALE_INV);
            // raw logits to gmem (coalesced float4 across tx)
            *(float4*)(simB + (size_t)(qt * 64 + row) * SEQ + kt * 64 + tx * 4) = lv;

            float tm = fmaxf(fmaxf(lv.x, lv.y), fmaxf(lv.z, lv.w));
            #pragma unroll
            for (int o = 8; o > 0; o >>= 1)
                tm = fmaxf(tm, __shfl_xor_sync(0xffffffffu, tm, o, 16));

            const float mo = m[i];
            const float mn = fmaxf(mo, tm);
            float ts = __expf(lv.x - mn) + __expf(lv.y - mn) +
                       __expf(lv.z - mn) + __expf(lv.w - mn);
            #pragma unroll
            for (int o = 8; o > 0; o >>= 1)
                ts += __shfl_xor_sync(0xffffffffu, ts, o, 16);

            den[i] = den[i] * __expf(mo - mn) + ts;
            m[i]   = mn;
        }
    }

    float inv[8];
    #pragma unroll
    for (int i = 0; i < 8; i++) inv[i] = 1.0f / den[i];

    // ---------------- Phase 2: normalize + P @ V ----------------
    u64 o2[4][4] = {};   // row-pairs x 4 dh cols
    for (int kt = 0; kt < 32; kt++) {
        __syncthreads();   // prior GEMM reads of sA/sB complete
        load_tile(sB, Vh + (size_t)kt * 64 * DHEAD, DHEAD, tid);

        // normalize; write probs; stage P transposed: Pt[key][qrow] in sA
        #pragma unroll
        for (int i = 0; i < 8; i++) {
            const int row = (i < 4) ? ty * 4 + i : 32 + ty * 4 + (i - 4);
            float* lp = simB + (size_t)(qt * 64 + row) * SEQ + kt * 64 + tx * 4;
            float4 l4 = *(const float4*)lp;
            float4 p;
            p.x = __expf(l4.x - m[i]) * inv[i];
            p.y = __expf(l4.y - m[i]) * inv[i];
            p.z = __expf(l4.z - m[i]) * inv[i];
            p.w = __expf(l4.w - m[i]) * inv[i];
            *(float4*)lp = p;

            const int qg = row >> 2, qo = row & 3;
            const int s = ((qg ^ (tx & 7)) << 2) + qo;    // (key>>2)&7 == tx for j<4
            sA[(tx * 4 + 0) * 64 + s] = p.x;
            sA[(tx * 4 + 1) * 64 + s] = p.y;
            sA[(tx * 4 + 2) * 64 + s] = p.z;
            sA[(tx * 4 + 3) * 64 + s] = p.w;
        }
        __syncthreads();

        // O += P @ V  (contraction over this tile's 64 keys)
        #pragma unroll 8
        for (int kk = 0; kk < 64; kk++) {
            float4 bv  = *(const float4*)&sB[swz(kk, tx)];      // V[kk][tx*4..+3]
            float4 a0f = *(const float4*)&sA[swz(kk, ty)];      // P^T: qrows ty*4..+3
            float4 a1f = *(const float4*)&sA[swz(kk, 8 + ty)];  // qrows 32+ty*4..+3
            u64 ap[4];
            f4u(a0f, ap[0], ap[1]);
            f4u(a1f, ap[2], ap[3]);
            u64 bd[4] = { pack2(bv.x, bv.x), pack2(bv.y, bv.y),
                          pack2(bv.z, bv.z), pack2(bv.w, bv.w) };
            #pragma unroll
            for (int ip = 0; ip < 4; ip++)
                #pragma unroll
                for (int j = 0; j < 4; j++)
                    o2[ip][j] = ffma2(ap[ip], bd[j], o2[ip][j]);
        }
    }

    // Write self_attn with the (0,2,1,3) transpose.
    #pragma unroll
    for (int i = 0; i < 8; i++) {
        const int row = (i < 4) ? ty * 4 + i : 32 + ty * 4 + (i - 4);
        const int ip  = (i >> 2) * 2 + ((i & 3) >> 1);
        const int sel = i & 1;
        float4 o;
        { float2 t = unpack2(o2[ip][0]); o.x = sel ? t.y : t.x; }
        { float2 t = unpack2(o2[ip][1]); o.y = sel ? t.y : t.x; }
        { float2 t = unpack2(o2[ip][2]); o.z = sel ? t.y : t.x; }
        { float2 t = unpack2(o2[ip][3]); o.w = sel ? t.y : t.x; }
        *(float4*)(out_attn + ((size_t)b * SEQ + qt * 64 + row) * DMODEL
                   + h * DHEAD + tx * 4) = o;
    }
}

// ---------------------------------------------------------------------------
extern "C" void kernel_launch(void* const* d_in, const int* in_sizes, int n_in,
                              void* d_out, int out_size)
{
    const float* seq = (const float*)d_in[0];
    const float* Wq  = (const float*)d_in[1];
    const float* Wk  = (const float*)d_in[2];
    const float* Wv  = (const float*)d_in[3];

    float* out_attn = (float*)d_out;
    float* out_sim  = (float*)d_out + (size_t)BATCH * SEQ * DMODEL;

    proj_kernel<<<dim3(DMODEL / 64, (BATCH * SEQ) / 64, 3), 128>>>(seq, Wq, Wk, Wv);
    attn_kernel<<<dim3(SEQ / 64, NHEAD, BATCH), 128>>>(out_attn, out_sim);
}

// round 3
// speedup vs baseline: 2.1291x; 1.9549x over previous
#include <cuda_runtime.h>

#define BATCH 2
#define SEQ   2048
#define DMODEL 1024
#define NHEAD 16
#define DHEAD 64
#define SCALE_INV 0.03125f   // 1/sqrt(1024)

// Scratch for projected Q,K,V (allocation-free rule: __device__ globals)
__device__ float g_Q[BATCH * SEQ * DMODEL];
__device__ float g_K[BATCH * SEQ * DMODEL];
__device__ float g_V[BATCH * SEQ * DMODEL];

// ---- tf32 helpers ----------------------------------------------------------
__device__ __forceinline__ unsigned tf32r(float x) {
    unsigned r; asm("cvt.rna.tf32.f32 %0, %1;" : "=r"(r) : "f"(x)); return r;
}

// mma.sync m16n8k8 tf32: D = A*B + D (fp32 accum)
__device__ __forceinline__ void mma8(float* c, const unsigned* a, unsigned b0, unsigned b1) {
    asm volatile(
        "mma.sync.aligned.m16n8k8.row.col.f32.tf32.tf32.f32 "
        "{%0,%1,%2,%3}, {%4,%5,%6,%7}, {%8,%9}, {%0,%1,%2,%3};"
        : "+f"(c[0]), "+f"(c[1]), "+f"(c[2]), "+f"(c[3])
        : "r"(a[0]), "r"(a[1]), "r"(a[2]), "r"(a[3]), "r"(b0), "r"(b1));
}

// XOR swizzle for [64][64] f32 tiles: keeps float4/float2 groups intact,
// makes cooperative loads and B-fragment LDS conflict-free.
__device__ __forceinline__ int off(int r, int c) {
    return r * 64 + (c ^ ((r & 7) << 2));
}

// Cooperative load of a 64x64 tile (row stride ldg) with tf32 rounding.
__device__ __forceinline__ void load_tile_tf32(float* S, const float* g, int ldg, int tid) {
    #pragma unroll
    for (int it = 0; it < 8; it++) {
        int i  = tid + it * 128;
        int r  = i >> 4;
        int c4 = (i & 15) << 2;
        float4 v = *(const float4*)(g + (size_t)r * ldg + c4);
        float4 t;
        t.x = __uint_as_float(tf32r(v.x));
        t.y = __uint_as_float(tf32r(v.y));
        t.z = __uint_as_float(tf32r(v.z));
        t.w = __uint_as_float(tf32r(v.w));
        *(float4*)&S[off(r, c4)] = t;
    }
}

// Compute 16x64 logit fragments for one warp: C[nt][4] += Arows @ Brows^T.
// A rows = warp*16 + (g, g+8); B rows (n) = nt*8 + g; contraction over 64 cols.
__device__ __forceinline__ void warp_gemm_64(
    float c[8][4], const float* sA, const float* sB, int warp, int lane)
{
    const int g   = lane >> 2;
    const int tig = lane & 3;
    const int ra  = warp * 16 + g;
    #pragma unroll
    for (int ks = 0; ks < 8; ks++) {
        const int k0 = ks * 8 + tig;
        unsigned a[4];
        a[0] = __float_as_uint(sA[off(ra,     k0)]);
        a[1] = __float_as_uint(sA[off(ra + 8, k0)]);
        a[2] = __float_as_uint(sA[off(ra,     k0 + 4)]);
        a[3] = __float_as_uint(sA[off(ra + 8, k0 + 4)]);
        #pragma unroll
        for (int nt = 0; nt < 8; nt++) {
            const int rb = nt * 8 + g;
            unsigned b0 = __float_as_uint(sB[off(rb, k0)]);
            unsigned b1 = __float_as_uint(sB[off(rb, k0 + 4)]);
            mma8(c[nt], a, b0, b1);
        }
    }
}

// ---------------------------------------------------------------------------
// Projection: Y = X @ W^T on tensor cores. 64x64 tile, 128 thr (4 warps).
// ---------------------------------------------------------------------------
__global__ __launch_bounds__(128) void proj_kernel(
    const float* __restrict__ X,
    const float* __restrict__ Wq,
    const float* __restrict__ Wk,
    const float* __restrict__ Wv)
{
    __shared__ float sA[4096];
    __shared__ float sB[4096];

    const int bz = blockIdx.z;
    const float* __restrict__ W = (bz == 0) ? Wq : (bz == 1) ? Wk : Wv;
    float* __restrict__ Y = (bz == 0) ? g_Q : (bz == 1) ? g_K : g_V;

    const int rowBase = blockIdx.y * 64;
    const int colBase = blockIdx.x * 64;
    const int tid  = threadIdx.x;
    const int warp = tid >> 5;
    const int lane = tid & 31;

    float c[8][4] = {};

    for (int k0 = 0; k0 < DMODEL; k0 += 64) {
        __syncthreads();
        load_tile_tf32(sA, X + (size_t)rowBase * DMODEL + k0, DMODEL, tid);
        load_tile_tf32(sB, W + (size_t)colBase * DMODEL + k0, DMODEL, tid);
        __syncthreads();
        warp_gemm_64(c, sA, sB, warp, lane);
    }

    const int g   = lane >> 2;
    const int tig = lane & 3;
    const int r0  = rowBase + warp * 16 + g;
    #pragma unroll
    for (int nt = 0; nt < 8; nt++) {
        const int col = colBase + nt * 8 + 2 * tig;
        *(float2*)(Y + (size_t)r0 * DMODEL + col)       = make_float2(c[nt][0], c[nt][1]);
        *(float2*)(Y + (size_t)(r0 + 8) * DMODEL + col) = make_float2(c[nt][2], c[nt][3]);
    }
}

// ---------------------------------------------------------------------------
// Attention per (b,h); head h's q/k/v are CONTIGUOUS [2048,64] matrices.
// 64-query tile, 128 threads (4 warps, 16 rows each), tensor-core GEMMs.
// Phase 1: running max/sum only (no gmem writes).
// Phase 2: recompute logits, write probs once, O += P@V.
// ---------------------------------------------------------------------------
__global__ __launch_bounds__(128) void attn_kernel(
    float* __restrict__ out_attn,   // [B, S, D]
    float* __restrict__ out_sim)    // [B, H, S, S]
{
    __shared__ float sQ[4096];
    __shared__ float sKV[4096];
    __shared__ float sP[4096];

    const int qt = blockIdx.x;      // 0..31
    const int h  = blockIdx.y;
    const int b  = blockIdx.z;

    const size_t headOff = ((size_t)b * SEQ + (size_t)h * 128) * DMODEL;
    const float* __restrict__ Qh = g_Q + headOff;
    const float* __restrict__ Kh = g_K + headOff;
    const float* __restrict__ Vh = g_V + headOff;
    float* __restrict__ simB = out_sim + (size_t)(b * NHEAD + h) * SEQ * SEQ;

    const int tid  = threadIdx.x;
    const int warp = tid >> 5;
    const int lane = tid & 31;
    const int g    = lane >> 2;
    const int tig  = lane & 3;

    load_tile_tf32(sQ, Qh + (size_t)qt * 64 * DHEAD, DHEAD, tid);

    float m0 = -1e30f, m1 = -1e30f, den0 = 0.0f, den1 = 0.0f;

    // ---------------- Phase 1: running max/sum ----------------
    for (int kt = 0; kt < 32; kt++) {
        __syncthreads();
        load_tile_tf32(sKV, Kh + (size_t)kt * 64 * DHEAD, DHEAD, tid);
        __syncthreads();

        float c[8][4] = {};
        warp_gemm_64(c, sQ, sKV, warp, lane);

        float t0 = -1e30f, t1 = -1e30f;
        #pragma unroll
        for (int nt = 0; nt < 8; nt++) {
            t0 = fmaxf(t0, fmaxf(c[nt][0], c[nt][1]));
            t1 = fmaxf(t1, fmaxf(c[nt][2], c[nt][3]));
        }
        t0 *= SCALE_INV; t1 *= SCALE_INV;
        #pragma unroll
        for (int o = 1; o < 4; o <<= 1) {
            t0 = fmaxf(t0, __shfl_xor_sync(0xffffffffu, t0, o, 4));
            t1 = fmaxf(t1, __shfl_xor_sync(0xffffffffu, t1, o, 4));
        }
        const float n0 = fmaxf(m0, t0), n1 = fmaxf(m1, t1);
        float s0 = 0.0f, s1 = 0.0f;
        #pragma unroll
        for (int nt = 0; nt < 8; nt++) {
            s0 += __expf(c[nt][0] * SCALE_INV - n0) + __expf(c[nt][1] * SCALE_INV - n0);
            s1 += __expf(c[nt][2] * SCALE_INV - n1) + __expf(c[nt][3] * SCALE_INV - n1);
        }
        #pragma unroll
        for (int o = 1; o < 4; o <<= 1) {
            s0 += __shfl_xor_sync(0xffffffffu, s0, o, 4);
            s1 += __shfl_xor_sync(0xffffffffu, s1, o, 4);
        }
        den0 = den0 * __expf(m0 - n0) + s0;  m0 = n0;
        den1 = den1 * __expf(m1 - n1) + s1;  m1 = n1;
    }

    const float inv0 = 1.0f / den0;
    const float inv1 = 1.0f / den1;

    // ---------------- Phase 2: recompute, write probs, O += P@V -------------
    float o2[8][4] = {};
    const int rloc = warp * 16 + g;              // local q-row (0..63)
    const int qrow = qt * 64 + rloc;             // global q-row

    for (int kt = 0; kt < 32; kt++) {
        __syncthreads();                          // prior V-mma done with sKV
        load_tile_tf32(sKV, Kh + (size_t)kt * 64 * DHEAD, DHEAD, tid);
        __syncthreads();

        float c[8][4] = {};
        warp_gemm_64(c, sQ, sKV, warp, lane);

        // probs: write to gmem, stage tf32 into sP (warp-local rows)
        #pragma unroll
        for (int nt = 0; nt < 8; nt++) {
            float p0 = __expf(c[nt][0] * SCALE_INV - m0) * inv0;
            float p1 = __expf(c[nt][1] * SCALE_INV - m0) * inv0;
            float p2 = __expf(c[nt][2] * SCALE_INV - m1) * inv1;
            float p3 = __expf(c[nt][3] * SCALE_INV - m1) * inv1;
            const int col = kt * 64 + nt * 8 + 2 * tig;
            *(float2*)(simB + (size_t)qrow * SEQ + col)       = make_float2(p0, p1);
            *(float2*)(simB + (size_t)(qrow + 8) * SEQ + col) = make_float2(p2, p3);
            const int lcol = nt * 8 + 2 * tig;
            float2 q0 = make_float2(__uint_as_float(tf32r(p0)), __uint_as_float(tf32r(p1)));
            float2 q1 = make_float2(__uint_as_float(tf32r(p2)), __uint_as_float(tf32r(p3)));
            *(float2*)&sP[off(rloc,     lcol)] = q0;
            *(float2*)&sP[off(rloc + 8, lcol)] = q1;
        }

        __syncthreads();                          // everyone done reading K
        load_tile_tf32(sKV, Vh + (size_t)kt * 64 * DHEAD, DHEAD, tid);
        __syncthreads();                          // V visible (sP warp-local: ok)

        // O += P @ V : A = sP rows (this warp), B[k][n] = V[key][dh]
        #pragma unroll
        for (int ks = 0; ks < 8; ks++) {
            const int k0 = ks * 8 + tig;
            unsigned a[4];
            a[0] = __float_as_uint(sP[off(rloc,     k0)]);
            a[1] = __float_as_uint(sP[off(rloc + 8, k0)]);
            a[2] = __float_as_uint(sP[off(rloc,     k0 + 4)]);
            a[3] = __float_as_uint(sP[off(rloc + 8, k0 + 4)]);
            #pragma unroll
            for (int nt = 0; nt < 8; nt++) {
                // b0 = V[k0][nt*8+g], b1 = V[k0+4][nt*8+g]
                unsigned b0 = __float_as_uint(sKV[off(ks * 8 + tig,     nt * 8 + g)]);
                unsigned b1 = __float_as_uint(sKV[off(ks * 8 + tig + 4, nt * 8 + g)]);
                mma8(o2[nt], a, b0, b1);
            }
        }
    }

    // Write self_attn with the (0,2,1,3) head transpose.
    #pragma unroll
    for (int nt = 0; nt < 8; nt++) {
        const int dh = h * DHEAD + nt * 8 + 2 * tig;
        *(float2*)(out_attn + ((size_t)b * SEQ + qrow) * DMODEL + dh)
            = make_float2(o2[nt][0], o2[nt][1]);
        *(float2*)(out_attn + ((size_t)b * SEQ + qrow + 8) * DMODEL + dh)
            = make_float2(o2[nt][2], o2[nt][3]);
    }
}

// ---------------------------------------------------------------------------
extern "C" void kernel_launch(void* const* d_in, const int* in_sizes, int n_in,
                              void* d_out, int out_size)
{
    const float* seq = (const float*)d_in[0];
    const float* Wq  = (const float*)d_in[1];
    const float* Wk  = (const float*)d_in[2];
    const float* Wv  = (const float*)d_in[3];

    float* out_attn = (float*)d_out;
    float* out_sim  = (float*)d_out + (size_t)BATCH * SEQ * DMODEL;

    proj_kernel<<<dim3(DMODEL / 64, (BATCH * SEQ) / 64, 3), 128>>>(seq, Wq, Wk, Wv);
    attn_kernel<<<dim3(SEQ / 64, NHEAD, BATCH), 128>>>(out_attn, out_sim);
}